// round 6
// baseline (speedup 1.0000x reference)
#include <cuda_runtime.h>
#include <cuda_fp16.h>
#include <math.h>
#include <stdint.h>

// Problem constants
#define BATCH   2
#define S_LEN   2048
#define HIDDEN  2048
#define NH      16
#define NKV     2
#define HD      128
#define REP     (NH / NKV)              // 8
#define QKV_COLS ((NH + 2 * NKV) * HD)  // 2560
#define ROWS    (BATCH * S_LEN)         // 4096
#define SCALE_F   0.08838834764831845f
#define SOFTCAP_F 30.0f

// Scratch (__device__ globals; 16B-aligned for cp.async/ldmatrix)
static __device__ __align__(16) __half g_hh[(size_t)ROWS * HIDDEN];
static __device__ __align__(16) __half g_wqkvh[(size_t)HIDDEN * QKV_COLS];
static __device__ __align__(16) __half g_woh[(size_t)HIDDEN * HIDDEN];
static __device__ __align__(16) __half g_qkvh[(size_t)ROWS * QKV_COLS];
static __device__ __align__(16) __half g_attnh[(size_t)ROWS * HIDDEN];
static __device__ float g_cos[S_LEN * 64];
static __device__ float g_sin[S_LEN * 64];

// ---------------------------------------------------------------------------
// PTX helpers
// ---------------------------------------------------------------------------
__device__ __forceinline__ void mma_f16(float* d, const uint32_t* a, const uint32_t* b) {
    asm volatile(
        "mma.sync.aligned.m16n8k16.row.col.f32.f16.f16.f32 "
        "{%0,%1,%2,%3}, {%4,%5,%6,%7}, {%8,%9}, {%0,%1,%2,%3};\n"
        : "+f"(d[0]), "+f"(d[1]), "+f"(d[2]), "+f"(d[3])
        : "r"(a[0]), "r"(a[1]), "r"(a[2]), "r"(a[3]), "r"(b[0]), "r"(b[1]));
}
__device__ __forceinline__ void ldsm4(uint32_t* r, uint32_t addr) {
    asm volatile("ldmatrix.sync.aligned.m8n8.x4.shared.b16 {%0,%1,%2,%3}, [%4];"
                 : "=r"(r[0]), "=r"(r[1]), "=r"(r[2]), "=r"(r[3]) : "r"(addr));
}
__device__ __forceinline__ void ldsm4t(uint32_t* r, uint32_t addr) {
    asm volatile("ldmatrix.sync.aligned.m8n8.x4.trans.shared.b16 {%0,%1,%2,%3}, [%4];"
                 : "=r"(r[0]), "=r"(r[1]), "=r"(r[2]), "=r"(r[3]) : "r"(addr));
}
#define CP_ASYNC16(dst32, src) \
    asm volatile("cp.async.cg.shared.global [%0], [%1], 16;\n" :: "r"(dst32), "l"(src))
#define CP_COMMIT() asm volatile("cp.async.commit_group;\n")
#define CP_WAIT0()  asm volatile("cp.async.wait_group 0;\n")
#define CP_WAIT1()  asm volatile("cp.async.wait_group 1;\n")

__device__ __forceinline__ uint32_t packh2(float a, float b) {
    __half2 h = __floats2half2_rn(a, b);
    return *reinterpret_cast<uint32_t*>(&h);
}

// Softcap 30*tanh(z/30) on the FMA pipe: deg-7 Taylor in w=z/30 (|w|<=0.35:
// err < 2e-6), rare predicated exact fallback for |w|>0.35.
__device__ __forceinline__ float softcap(float z) {
    float w  = z * (1.0f / SOFTCAP_F);
    float w2 = w * w;
    float p  = fmaf(-0.05396825397f, w2, 0.13333333333f);   // -17/315, 2/15
    p        = fmaf(p, w2, -0.33333333333f);                 // -1/3
    float t  = fmaf(p * w2, w, w);                           // w + w^3*(...)
    if (fabsf(w) > 0.35f) {
        float u = __expf(-2.0f * w);
        t = __fdividef(1.0f - u, 1.0f + u);
    }
    return SOFTCAP_F * t;
}

// ---------------------------------------------------------------------------
// f32 -> f16 conversion, 8 elems/thread
// ---------------------------------------------------------------------------
__global__ void f2h_kernel(const float* __restrict__ in, __half* __restrict__ out, int n8) {
    int i = blockIdx.x * blockDim.x + threadIdx.x;
    if (i < n8) {
        float4 a = ((const float4*)in)[2 * i];
        float4 b = ((const float4*)in)[2 * i + 1];
        uint4 u;
        u.x = packh2(a.x, a.y); u.y = packh2(a.z, a.w);
        u.z = packh2(b.x, b.y); u.w = packh2(b.z, b.w);
        ((uint4*)out)[i] = u;
    }
}

// ---------------------------------------------------------------------------
// RoPE table via double rotation recurrence: 64 pows + 2048 trig inits total,
// then 64 dependent DFMA steps per thread. Accurate and cheap.
// grid = 64 blocks (one per d), 32 threads (strided over s).
// ---------------------------------------------------------------------------
__global__ void rope_table_kernel() {
    int d = blockIdx.x, t = threadIdx.x;
    double invf = 0.0;
    if (t == 0) invf = pow(10000.0, -(double)d / 64.0);
    {
        int lo = __shfl_sync(0xffffffffu, __double2loint(invf), 0);
        int hi = __shfl_sync(0xffffffffu, __double2hiint(invf), 0);
        invf = __hiloint2double(hi, lo);
    }
    double a0 = (double)t * invf;
    double c = cos(a0), s = sin(a0);
    double step = 32.0 * invf;
    double cs = cos(step), ss = sin(step);
    for (int i = t; i < S_LEN; i += 32) {
        g_cos[(i << 6) + d] = (float)c;
        g_sin[(i << 6) + d] = (float)s;
        double nc = c * cs - s * ss;
        double ns = c * ss + s * cs;
        c = nc; s = ns;
    }
}

// RoPE applied in-place on the half qkv buffer (Q heads 0-15, K heads 16-17).
__global__ void rope_apply_h(__half* __restrict__ q) {
    int i = blockIdx.x * blockDim.x + threadIdx.x;
    const int total = ROWS * 18 * 32;
    if (i >= total) return;
    int dp   = (i & 31) * 2;
    int rest = i >> 5;
    int hh   = rest % 18;
    int row  = rest / 18;
    int s    = row & (S_LEN - 1);
    size_t base = (size_t)row * QKV_COLS +
                  (hh < 16 ? (size_t)hh * HD : (size_t)(NH * HD) + (size_t)(hh - 16) * HD);
    float2 c  = *(const float2*)&g_cos[(s << 6) + dp];
    float2 sn = *(const float2*)&g_sin[(s << 6) + dp];
    float2 x1 = __half22float2(*(__half2*)&q[base + dp]);
    float2 x2 = __half22float2(*(__half2*)&q[base + dp + 64]);
    *(__half2*)&q[base + dp]      = __floats2half2_rn(x1.x * c.x - x2.x * sn.x,
                                                      x1.y * c.y - x2.y * sn.y);
    *(__half2*)&q[base + dp + 64] = __floats2half2_rn(x1.x * sn.x + x2.x * c.x,
                                                      x1.y * sn.y + x2.y * c.y);
}

// ---------------------------------------------------------------------------
// FP16 GEMM (f32 accumulate), 3-stage cp.async pipeline, ONE barrier per tile.
// C[M,N] = A[M,K] @ B[K,N], both half row-major.
// BM=BN=128, BK=32, 256 threads = 8 warps (4x2), warp tile 32x64.
// ---------------------------------------------------------------------------
#define GA_ST (128 * 40 * 2)   // A stage bytes (stride 40 halves)
#define GB_ST (32 * 136 * 2)   // B stage bytes (stride 136 halves)
#define GEMM_SMEM_BYTES (3 * (GA_ST + GB_ST))

template <bool OUTHALF>
__global__ __launch_bounds__(256, 2)
void gemm_f16(const __half* __restrict__ A, const __half* __restrict__ B,
              void* __restrict__ Cv, int M, int N, int K) {
    extern __shared__ __align__(16) char gsm[];
    const uint32_t sbase = (uint32_t)__cvta_generic_to_shared(gsm);

    const int tid = threadIdx.x, lane = tid & 31, warp = tid >> 5;
    const int wm = warp >> 1, wn = warp & 1, g4 = lane >> 2, t4 = lane & 3;

    const __half* Ab = A + (size_t)blockIdx.y * 128 * K;
    const __half* Bb = B + (size_t)blockIdx.x * 128;

    // ldmatrix lane geometry
    const int lsub  = lane >> 3;
    const int arow  = ((lsub & 1) << 3) + (lane & 7);
    const int acolh = (lsub >> 1) << 3;
    const int vrow  = lane & 15;
    const int vcolh = (lane >> 4) << 3;

    const int aR = tid >> 2, aC = tid & 3;        // A: row, 16B chunk
    const int bR = tid >> 4, bC = tid & 15;       // B: row, 16B chunk

    auto issue = [&](int t, int st) {
        uint32_t sA = sbase + st * (GA_ST + GB_ST);
        uint32_t sB = sA + GA_ST;
#pragma unroll
        for (int i = 0; i < 2; i++) {
            int r = aR + 64 * i;
            CP_ASYNC16(sA + r * 80 + aC * 16, Ab + (size_t)r * K + t * 32 + aC * 8);
        }
#pragma unroll
        for (int i = 0; i < 2; i++) {
            int r = bR + 16 * i;
            CP_ASYNC16(sB + r * 272 + bC * 16, Bb + (size_t)(t * 32 + r) * N + bC * 8);
        }
        CP_COMMIT();
    };

    float acc[2][8][4];
#pragma unroll
    for (int mt = 0; mt < 2; mt++)
#pragma unroll
        for (int nt = 0; nt < 8; nt++)
#pragma unroll
            for (int r = 0; r < 4; r++) acc[mt][nt][r] = 0.0f;

    const int T = K / 32;
    issue(0, 0);
    issue(1, 1);

    for (int t = 0; t < T; t++) {
        const int cur = t % 3;
        if (t < T - 1) { CP_WAIT1(); } else { CP_WAIT0(); }
        __syncthreads();
        if (t + 2 < T) issue(t + 2, (t + 2) % 3);

        const uint32_t sA = sbase + cur * (GA_ST + GB_ST);
        const uint32_t sB = sA + GA_ST;
#pragma unroll
        for (int ks = 0; ks < 2; ks++) {
            uint32_t af[2][4];
#pragma unroll
            for (int mt = 0; mt < 2; mt++)
                ldsm4(af[mt], sA + (wm * 32 + mt * 16 + arow) * 80 + (ks * 16 + acolh) * 2);
            uint32_t bf[8][2];
#pragma unroll
            for (int tt = 0; tt < 4; tt++) {
                uint32_t v[4];
                ldsm4t(v, sB + (ks * 16 + vrow) * 272 + (wn * 64 + tt * 16 + vcolh) * 2);
                bf[2 * tt][0] = v[0]; bf[2 * tt][1] = v[1];
                bf[2 * tt + 1][0] = v[2]; bf[2 * tt + 1][1] = v[3];
            }
#pragma unroll
            for (int mt = 0; mt < 2; mt++)
#pragma unroll
                for (int nt = 0; nt < 8; nt++)
                    mma_f16(acc[mt][nt], af[mt], bf[nt]);
        }
        // no trailing barrier: next iteration's wait+sync protects stage reuse
    }

#pragma unroll
    for (int mt = 0; mt < 2; mt++) {
        int r0 = blockIdx.y * 128 + wm * 32 + mt * 16 + g4;
#pragma unroll
        for (int nt = 0; nt < 8; nt++) {
            int c = blockIdx.x * 128 + wn * 64 + nt * 8 + 2 * t4;
            if (OUTHALF) {
                __half* C = (__half*)Cv;
                *(__half2*)(C + (size_t)r0 * N + c)       = __floats2half2_rn(acc[mt][nt][0], acc[mt][nt][1]);
                *(__half2*)(C + (size_t)(r0 + 8) * N + c) = __floats2half2_rn(acc[mt][nt][2], acc[mt][nt][3]);
            } else {
                float* C = (float*)Cv;
                *(float2*)(C + (size_t)r0 * N + c)       = make_float2(acc[mt][nt][0], acc[mt][nt][1]);
                *(float2*)(C + (size_t)(r0 + 8) * N + c) = make_float2(acc[mt][nt][2], acc[mt][nt][3]);
            }
        }
    }
}

// ---------------------------------------------------------------------------
// FP16 flash attention, warp-owns-full-row layout, 3-stage K/V pipeline.
// BM=128 Q rows, BN=64 keys, 256 threads = 8 warps; warp tile = 16 rows x 64 keys.
// Row softmax in quad shuffles; P in registers; polynomial softcap (no MUFU).
// One __syncthreads per KV tile.
// ---------------------------------------------------------------------------
#define AQ_B 272                        // 136 halves per row
#define AOFF_Q   0
#define AOFF_KV  34816                  // after Q (128*272)
#define AKV_ST   34816                  // per stage: K 17408 + V 17408
#define ATTN_SMEM_BYTES (AOFF_KV + 3 * AKV_ST)   // 139264

__global__ __launch_bounds__(256, 1)
void attn_kernel(const __half* __restrict__ qkv, __half* __restrict__ out) {
    extern __shared__ __align__(16) char smraw[];
    const uint32_t sbase = (uint32_t)__cvta_generic_to_shared(smraw);

    const int qb = (int)gridDim.x - 1 - (int)blockIdx.x;  // longest first
    const int h  = blockIdx.y;
    const int b  = blockIdx.z;
    const int g  = h / REP;

    const int tid = threadIdx.x, lane = tid & 31, warp = tid >> 5;
    const int g4 = lane >> 2, t4 = lane & 3;

    const size_t rs = QKV_COLS;
    const __half* qbase = qkv + ((size_t)b * S_LEN + (size_t)qb * 128) * rs + (size_t)h * HD;
    const __half* kbase = qkv + (size_t)b * S_LEN * rs + (size_t)(NH * HD) + (size_t)g * HD;
    const __half* vbase = kbase + (size_t)(NKV * HD);

    // ldmatrix lane geometry
    const int lsub  = lane >> 3;
    const int arow  = ((lsub & 1) << 3) + (lane & 7);
    const int acolh = (lsub >> 1) << 3;
    const int krow  = ((lane >> 4) << 3) + (lane & 7);
    const int kcolh = ((lane >> 3) & 1) << 3;
    const int vrow  = lane & 15;
    const int vcolh = (lane >> 4) << 3;

    auto issueKV = [&](int kt, int st) {
        const __half* kb = kbase + (size_t)kt * 64 * rs;
        const __half* vb = vbase + (size_t)kt * 64 * rs;
        const uint32_t kd = sbase + AOFF_KV + st * AKV_ST;
        const uint32_t vd = kd + 17408;
#pragma unroll
        for (int i = 0; i < 4; i++) {
            int idx = tid + 256 * i;
            int r = idx >> 4, ch = idx & 15;
            CP_ASYNC16(kd + r * AQ_B + ch * 16, kb + (size_t)r * rs + ch * 8);
            CP_ASYNC16(vd + r * AQ_B + ch * 16, vb + (size_t)r * rs + ch * 8);
        }
        CP_COMMIT();
    };

    // prologue: group0 = Q + KV tile0, group1 = KV tile1
    {
#pragma unroll
        for (int i = 0; i < 8; i++) {
            int idx = tid + 256 * i;
            int r = idx >> 4, ch = idx & 15;
            CP_ASYNC16(sbase + AOFF_Q + r * AQ_B + ch * 16, qbase + (size_t)r * rs + ch * 8);
        }
        const uint32_t kd = sbase + AOFF_KV;
        const uint32_t vd = kd + 17408;
#pragma unroll
        for (int i = 0; i < 4; i++) {
            int idx = tid + 256 * i;
            int r = idx >> 4, ch = idx & 15;
            CP_ASYNC16(kd + r * AQ_B + ch * 16, kbase + (size_t)r * rs + ch * 8);
            CP_ASYNC16(vd + r * AQ_B + ch * 16, vbase + (size_t)r * rs + ch * 8);
        }
        CP_COMMIT();
        issueKV(1, 1);   // ktmax = 2qb+1 >= 1 always
    }

    float m0 = -1e30f, m1 = -1e30f, l0 = 0.0f, l1 = 0.0f;
    float o[16][4];
#pragma unroll
    for (int nt = 0; nt < 16; nt++)
#pragma unroll
        for (int r = 0; r < 4; r++) o[nt][r] = 0.0f;

    const uint32_t aQ = sbase + AOFF_Q + (warp * 16 + arow) * AQ_B + acolh * 2;
    const int grow0 = qb * 128 + warp * 16 + g4;   // global rows (g4, g4+8)
    const int ktmax = 2 * qb + 1;

    for (int kt = 0; kt <= ktmax; kt++) {
        const int st = kt % 3;
        if (kt < ktmax) { CP_WAIT1(); } else { CP_WAIT0(); }
        __syncthreads();   // stage st ready; all warps done with stage being reissued

        if (kt + 2 <= ktmax) issueKV(kt + 2, (kt + 2) % 3);

        const uint32_t kSt = sbase + AOFF_KV + st * AKV_ST;
        const uint32_t bK = kSt + krow * AQ_B + kcolh * 2;
        const uint32_t bV = kSt + 17408 + vrow * AQ_B + vcolh * 2;

        // ---- S = Q K^T : 16 rows x 64 keys per warp ----
        float sfr[8][4];
#pragma unroll
        for (int nt = 0; nt < 8; nt++)
#pragma unroll
            for (int r = 0; r < 4; r++) sfr[nt][r] = 0.0f;

#pragma unroll
        for (int ks = 0; ks < 8; ks++) {
            uint32_t af[4];
            ldsm4(af, aQ + ks * 32);
#pragma unroll
            for (int nt2 = 0; nt2 < 4; nt2++) {
                uint32_t bb[4];
                ldsm4(bb, bK + nt2 * 16 * AQ_B + ks * 32);
                mma_f16(sfr[2 * nt2],     af, &bb[0]);
                mma_f16(sfr[2 * nt2 + 1], af, &bb[2]);
            }
        }

        // ---- polynomial softcap + causal + row softmax (quad-only) ----
        const bool diag = (kt >= 2 * qb);
        float mx0 = -1e30f, mx1 = -1e30f;
#pragma unroll
        for (int nt = 0; nt < 8; nt++) {
            int gk = kt * 64 + nt * 8 + 2 * t4;
#pragma unroll
            for (int j = 0; j < 2; j++) {
                float v0 = softcap(sfr[nt][j]     * SCALE_F);
                float v1 = softcap(sfr[nt][2 + j] * SCALE_F);
                if (diag && (gk + j) > grow0)     v0 = -1e30f;
                if (diag && (gk + j) > grow0 + 8) v1 = -1e30f;
                sfr[nt][j] = v0; sfr[nt][2 + j] = v1;
                mx0 = fmaxf(mx0, v0); mx1 = fmaxf(mx1, v1);
            }
        }
        mx0 = fmaxf(mx0, __shfl_xor_sync(0xffffffffu, mx0, 1));
        mx0 = fmaxf(mx0, __shfl_xor_sync(0xffffffffu, mx0, 2));
        mx1 = fmaxf(mx1, __shfl_xor_sync(0xffffffffu, mx1, 1));
        mx1 = fmaxf(mx1, __shfl_xor_sync(0xffffffffu, mx1, 2));

        float mn0 = fmaxf(m0, mx0);
        float mn1 = fmaxf(m1, mx1);
        float corr0 = __expf(m0 - mn0);
        float corr1 = __expf(m1 - mn1);
        m0 = mn0; m1 = mn1;

        float sum0 = 0.0f, sum1 = 0.0f;
#pragma unroll
        for (int nt = 0; nt < 8; nt++) {
            float p00 = __expf(sfr[nt][0] - mn0);
            float p01 = __expf(sfr[nt][1] - mn0);
            float p10 = __expf(sfr[nt][2] - mn1);
            float p11 = __expf(sfr[nt][3] - mn1);
            sum0 += p00 + p01; sum1 += p10 + p11;
            sfr[nt][0] = p00; sfr[nt][1] = p01;
            sfr[nt][2] = p10; sfr[nt][3] = p11;
        }
        l0 = l0 * corr0 + sum0;
        l1 = l1 * corr1 + sum1;

#pragma unroll
        for (int nt = 0; nt < 16; nt++) {
            o[nt][0] *= corr0; o[nt][1] *= corr0;
            o[nt][2] *= corr1; o[nt][3] *= corr1;
        }

        // ---- O += P @ V : P straight from registers ----
#pragma unroll
        for (int kk = 0; kk < 4; kk++) {
            uint32_t af[4];
            af[0] = packh2(sfr[2 * kk][0],     sfr[2 * kk][1]);
            af[1] = packh2(sfr[2 * kk][2],     sfr[2 * kk][3]);
            af[2] = packh2(sfr[2 * kk + 1][0], sfr[2 * kk + 1][1]);
            af[3] = packh2(sfr[2 * kk + 1][2], sfr[2 * kk + 1][3]);
#pragma unroll
            for (int tt = 0; tt < 8; tt++) {
                uint32_t v[4];
                ldsm4t(v, bV + kk * 16 * AQ_B + tt * 32);
                mma_f16(o[2 * tt],     af, &v[0]);
                mma_f16(o[2 * tt + 1], af, &v[2]);
            }
        }
    }

    // finalize: quad-reduce l, normalize, write
    l0 += __shfl_xor_sync(0xffffffffu, l0, 1);
    l0 += __shfl_xor_sync(0xffffffffu, l0, 2);
    l1 += __shfl_xor_sync(0xffffffffu, l1, 1);
    l1 += __shfl_xor_sync(0xffffffffu, l1, 2);
    float inv0 = 1.0f / l0;
    float inv1 = 1.0f / l1;

    size_t gr0 = (size_t)b * S_LEN + grow0;
#pragma unroll
    for (int nt = 0; nt < 16; nt++) {
        int c = h * HD + nt * 8 + 2 * t4;
        *(__half2*)(out + gr0 * HIDDEN + c)       = __floats2half2_rn(o[nt][0] * inv0, o[nt][1] * inv0);
        *(__half2*)(out + (gr0 + 8) * HIDDEN + c) = __floats2half2_rn(o[nt][2] * inv1, o[nt][3] * inv1);
    }
}

// ---------------------------------------------------------------------------
// Launch
// ---------------------------------------------------------------------------
extern "C" void kernel_launch(void* const* d_in, const int* in_sizes, int n_in,
                              void* d_out, int out_size) {
    (void)in_sizes; (void)n_in; (void)out_size;
    const float* hidden = (const float*)d_in[0];
    const float* Wqkv   = (const float*)d_in[1];
    const float* Wo     = (const float*)d_in[2];
    float* out = (float*)d_out;

    void* p;
    cudaGetSymbolAddress(&p, g_hh);    __half* hh    = (__half*)p;
    cudaGetSymbolAddress(&p, g_wqkvh); __half* wqkvh = (__half*)p;
    cudaGetSymbolAddress(&p, g_woh);   __half* woh   = (__half*)p;
    cudaGetSymbolAddress(&p, g_qkvh);  __half* qkvh  = (__half*)p;
    cudaGetSymbolAddress(&p, g_attnh); __half* attnh = (__half*)p;

    cudaFuncSetAttribute(attn_kernel, cudaFuncAttributeMaxDynamicSharedMemorySize,
                         ATTN_SMEM_BYTES);
    cudaFuncSetAttribute(gemm_f16<true>, cudaFuncAttributeMaxDynamicSharedMemorySize,
                         GEMM_SMEM_BYTES);
    cudaFuncSetAttribute(gemm_f16<false>, cudaFuncAttributeMaxDynamicSharedMemorySize,
                         GEMM_SMEM_BYTES);

    rope_table_kernel<<<64, 32>>>();

    // convert inputs to half (8 elems/thread)
    {
        int n8;
        n8 = ROWS * HIDDEN / 8;
        f2h_kernel<<<(n8 + 255) / 256, 256>>>(hidden, hh, n8);
        n8 = HIDDEN * QKV_COLS / 8;
        f2h_kernel<<<(n8 + 255) / 256, 256>>>(Wqkv, wqkvh, n8);
        n8 = HIDDEN * HIDDEN / 8;
        f2h_kernel<<<(n8 + 255) / 256, 256>>>(Wo, woh, n8);
    }

    // 1) QKV projection (half output)
    gemm_f16<true><<<dim3(QKV_COLS / 128, ROWS / 128), 256, GEMM_SMEM_BYTES>>>(
        hh, wqkvh, qkvh, ROWS, QKV_COLS, HIDDEN);
    // 2) RoPE on Q + K in place (half)
    {
        int total = ROWS * 18 * 32;
        rope_apply_h<<<(total + 255) / 256, 256>>>(qkvh);
    }
    // 3) Flash attention
    attn_kernel<<<dim3(S_LEN / 128, NH, BATCH), 256, ATTN_SMEM_BYTES>>>(qkvh, attnh);

    // 4) Output projection (float output)
    gemm_f16<false><<<dim3(HIDDEN / 128, ROWS / 128), 256, GEMM_SMEM_BYTES>>>(
        attnh, woh, out, ROWS, HIDDEN, HIDDEN);
}

// round 8
// speedup vs baseline: 1.0205x; 1.0205x over previous
#include <cuda_runtime.h>
#include <cuda_fp16.h>
#include <math.h>
#include <stdint.h>

// Problem constants
#define BATCH   2
#define S_LEN   2048
#define HIDDEN  2048
#define NH      16
#define NKV     2
#define HD      128
#define REP     (NH / NKV)              // 8
#define QKV_COLS ((NH + 2 * NKV) * HD)  // 2560
#define ROWS    (BATCH * S_LEN)         // 4096
#define SCALE_F   0.08838834764831845f
#define SOFTCAP_F 30.0f

// Scratch (__device__ globals; 16B-aligned for cp.async/ldmatrix)
static __device__ __align__(16) __half g_hh[(size_t)ROWS * HIDDEN];
static __device__ __align__(16) __half g_wqkvh[(size_t)HIDDEN * QKV_COLS];
static __device__ __align__(16) __half g_woh[(size_t)HIDDEN * HIDDEN];
static __device__ __align__(16) __half g_qkvh[(size_t)ROWS * QKV_COLS];
static __device__ __align__(16) __half g_attnh[(size_t)ROWS * HIDDEN];
static __device__ float g_cos[S_LEN * 64];
static __device__ float g_sin[S_LEN * 64];

// ---------------------------------------------------------------------------
// PTX helpers
// ---------------------------------------------------------------------------
__device__ __forceinline__ void mma_f16(float* d, const uint32_t* a, const uint32_t* b) {
    asm volatile(
        "mma.sync.aligned.m16n8k16.row.col.f32.f16.f16.f32 "
        "{%0,%1,%2,%3}, {%4,%5,%6,%7}, {%8,%9}, {%0,%1,%2,%3};\n"
        : "+f"(d[0]), "+f"(d[1]), "+f"(d[2]), "+f"(d[3])
        : "r"(a[0]), "r"(a[1]), "r"(a[2]), "r"(a[3]), "r"(b[0]), "r"(b[1]));
}
__device__ __forceinline__ void ldsm4(uint32_t* r, uint32_t addr) {
    asm volatile("ldmatrix.sync.aligned.m8n8.x4.shared.b16 {%0,%1,%2,%3}, [%4];"
                 : "=r"(r[0]), "=r"(r[1]), "=r"(r[2]), "=r"(r[3]) : "r"(addr));
}
__device__ __forceinline__ void ldsm4t(uint32_t* r, uint32_t addr) {
    asm volatile("ldmatrix.sync.aligned.m8n8.x4.trans.shared.b16 {%0,%1,%2,%3}, [%4];"
                 : "=r"(r[0]), "=r"(r[1]), "=r"(r[2]), "=r"(r[3]) : "r"(addr));
}
#define CP_ASYNC16(dst32, src) \
    asm volatile("cp.async.cg.shared.global [%0], [%1], 16;\n" :: "r"(dst32), "l"(src))
#define CP_COMMIT() asm volatile("cp.async.commit_group;\n")
#define CP_WAIT0()  asm volatile("cp.async.wait_group 0;\n")
#define CP_WAIT1()  asm volatile("cp.async.wait_group 1;\n")
#define CP_WAIT2()  asm volatile("cp.async.wait_group 2;\n")

__device__ __forceinline__ uint32_t packh2(float a, float b) {
    __half2 h = __floats2half2_rn(a, b);
    return *reinterpret_cast<uint32_t*>(&h);
}

// ---------------------------------------------------------------------------
// f32 -> f16 conversion, 8 elems/thread
// ---------------------------------------------------------------------------
__global__ void f2h_kernel(const float* __restrict__ in, __half* __restrict__ out, int n8) {
    int i = blockIdx.x * blockDim.x + threadIdx.x;
    if (i < n8) {
        float4 a = ((const float4*)in)[2 * i];
        float4 b = ((const float4*)in)[2 * i + 1];
        uint4 u;
        u.x = packh2(a.x, a.y); u.y = packh2(a.z, a.w);
        u.z = packh2(b.x, b.y); u.w = packh2(b.z, b.w);
        ((uint4*)out)[i] = u;
    }
}

// ---------------------------------------------------------------------------
// RoPE table via double rotation recurrence (cheap, fast-math-proof).
// ---------------------------------------------------------------------------
__global__ void rope_table_kernel() {
    int d = blockIdx.x, t = threadIdx.x;
    double invf = 0.0;
    if (t == 0) invf = pow(10000.0, -(double)d / 64.0);
    {
        int lo = __shfl_sync(0xffffffffu, __double2loint(invf), 0);
        int hi = __shfl_sync(0xffffffffu, __double2hiint(invf), 0);
        invf = __hiloint2double(hi, lo);
    }
    double a0 = (double)t * invf;
    double c = cos(a0), s = sin(a0);
    double step = 32.0 * invf;
    double cs = cos(step), ss = sin(step);
    for (int i = t; i < S_LEN; i += 32) {
        g_cos[(i << 6) + d] = (float)c;
        g_sin[(i << 6) + d] = (float)s;
        double nc = c * cs - s * ss;
        double ns = c * ss + s * cs;
        c = nc; s = ns;
    }
}

// RoPE applied in-place on the half qkv buffer (Q heads 0-15, K heads 16-17).
__global__ void rope_apply_h(__half* __restrict__ q) {
    int i = blockIdx.x * blockDim.x + threadIdx.x;
    const int total = ROWS * 18 * 32;
    if (i >= total) return;
    int dp   = (i & 31) * 2;
    int rest = i >> 5;
    int hh   = rest % 18;
    int row  = rest / 18;
    int s    = row & (S_LEN - 1);
    size_t base = (size_t)row * QKV_COLS +
                  (hh < 16 ? (size_t)hh * HD : (size_t)(NH * HD) + (size_t)(hh - 16) * HD);
    float2 c  = *(const float2*)&g_cos[(s << 6) + dp];
    float2 sn = *(const float2*)&g_sin[(s << 6) + dp];
    float2 x1 = __half22float2(*(__half2*)&q[base + dp]);
    float2 x2 = __half22float2(*(__half2*)&q[base + dp + 64]);
    *(__half2*)&q[base + dp]      = __floats2half2_rn(x1.x * c.x - x2.x * sn.x,
                                                      x1.y * c.y - x2.y * sn.y);
    *(__half2*)&q[base + dp + 64] = __floats2half2_rn(x1.x * sn.x + x2.x * c.x,
                                                      x1.y * sn.y + x2.y * c.y);
}

// ---------------------------------------------------------------------------
// FP16 GEMM (f32 accumulate), 3-stage cp.async pipeline (R5 structure,
// with the last-iteration wait race fixed).
// C[M,N] = A[M,K] @ B[K,N], both half row-major.
// BM=BN=128, BK=32, 256 threads = 8 warps (4x2), warp tile 32x64.
// ---------------------------------------------------------------------------
#define GA_ST (128 * 40 * 2)   // A stage bytes (stride 40 halves)
#define GB_ST (32 * 136 * 2)   // B stage bytes (stride 136 halves)
#define GEMM_SMEM_BYTES (3 * (GA_ST + GB_ST))

template <bool OUTHALF>
__global__ __launch_bounds__(256, 2)
void gemm_f16(const __half* __restrict__ A, const __half* __restrict__ B,
              void* __restrict__ Cv, int M, int N, int K) {
    extern __shared__ __align__(16) char gsm[];
    const uint32_t sbase = (uint32_t)__cvta_generic_to_shared(gsm);

    const int tid = threadIdx.x, lane = tid & 31, warp = tid >> 5;
    const int wm = warp >> 1, wn = warp & 1, g4 = lane >> 2, t4 = lane & 3;

    const __half* Ab = A + (size_t)blockIdx.y * 128 * K;
    const __half* Bb = B + (size_t)blockIdx.x * 128;

    const int lsub  = lane >> 3;
    const int arow  = ((lsub & 1) << 3) + (lane & 7);
    const int acolh = (lsub >> 1) << 3;
    const int vrow  = lane & 15;
    const int vcolh = (lane >> 4) << 3;

    const int aR = tid >> 2, aC = tid & 3;
    const int bR = tid >> 4, bC = tid & 15;

    auto issue = [&](int t, int st) {
        uint32_t sA = sbase + st * (GA_ST + GB_ST);
        uint32_t sB = sA + GA_ST;
#pragma unroll
        for (int i = 0; i < 2; i++) {
            int r = aR + 64 * i;
            CP_ASYNC16(sA + r * 80 + aC * 16, Ab + (size_t)r * K + t * 32 + aC * 8);
        }
#pragma unroll
        for (int i = 0; i < 2; i++) {
            int r = bR + 16 * i;
            CP_ASYNC16(sB + r * 272 + bC * 16, Bb + (size_t)(t * 32 + r) * N + bC * 8);
        }
        CP_COMMIT();
    };

    float acc[2][8][4];
#pragma unroll
    for (int mt = 0; mt < 2; mt++)
#pragma unroll
        for (int nt = 0; nt < 8; nt++)
#pragma unroll
            for (int r = 0; r < 4; r++) acc[mt][nt][r] = 0.0f;

    const int T = K / 32;
    issue(0, 0);
    issue(1, 1);

    for (int t = 0; t < T; t++) {
        const int cur = t % 3;
        if (t < T - 1) { CP_WAIT1(); } else { CP_WAIT0(); }
        __syncthreads();
        if (t + 2 < T) issue(t + 2, (t + 2) % 3);

        const uint32_t sA = sbase + cur * (GA_ST + GB_ST);
        const uint32_t sB = sA + GA_ST;
#pragma unroll
        for (int ks = 0; ks < 2; ks++) {
            uint32_t af[2][4];
#pragma unroll
            for (int mt = 0; mt < 2; mt++)
                ldsm4(af[mt], sA + (wm * 32 + mt * 16 + arow) * 80 + (ks * 16 + acolh) * 2);
            uint32_t bf[8][2];
#pragma unroll
            for (int tt = 0; tt < 4; tt++) {
                uint32_t v[4];
                ldsm4t(v, sB + (ks * 16 + vrow) * 272 + (wn * 64 + tt * 16 + vcolh) * 2);
                bf[2 * tt][0] = v[0]; bf[2 * tt][1] = v[1];
                bf[2 * tt + 1][0] = v[2]; bf[2 * tt + 1][1] = v[3];
            }
#pragma unroll
            for (int mt = 0; mt < 2; mt++)
#pragma unroll
                for (int nt = 0; nt < 8; nt++)
                    mma_f16(acc[mt][nt], af[mt], bf[nt]);
        }
        __syncthreads();
    }

#pragma unroll
    for (int mt = 0; mt < 2; mt++) {
        int r0 = blockIdx.y * 128 + wm * 32 + mt * 16 + g4;
#pragma unroll
        for (int nt = 0; nt < 8; nt++) {
            int c = blockIdx.x * 128 + wn * 64 + nt * 8 + 2 * t4;
            if (OUTHALF) {
                __half* C = (__half*)Cv;
                *(__half2*)(C + (size_t)r0 * N + c)       = __floats2half2_rn(acc[mt][nt][0], acc[mt][nt][1]);
                *(__half2*)(C + (size_t)(r0 + 8) * N + c) = __floats2half2_rn(acc[mt][nt][2], acc[mt][nt][3]);
            } else {
                float* C = (float*)Cv;
                *(float2*)(C + (size_t)r0 * N + c)       = make_float2(acc[mt][nt][0], acc[mt][nt][1]);
                *(float2*)(C + (size_t)(r0 + 8) * N + c) = make_float2(acc[mt][nt][2], acc[mt][nt][3]);
            }
        }
    }
}

// ---------------------------------------------------------------------------
// FP16 flash attention, warp-owns-full-row layout, DELAYED-PV pipeline:
// at iteration kt: S(kt) mma, then PV(kt-1) mma interleaved with softmax(kt)
// (independent -> ptxas overlaps tensor and fma pipes). P packed in registers.
// 4-stage KV ring (prefetch depth 2), one __syncthreads per tile.
// ---------------------------------------------------------------------------
#define AQ_B 272                        // 136 halves per row
#define AOFF_Q   0
#define AOFF_ST  34816                  // after Q (128*272)
#define AST      34816                  // per stage: K 17408 + V 17408
#define ATTN_SMEM_BYTES (AOFF_ST + 4 * AST)   // 174080

__global__ __launch_bounds__(256, 1)
void attn_kernel(const __half* __restrict__ qkv, __half* __restrict__ out) {
    extern __shared__ __align__(16) char smraw[];
    const uint32_t sbase = (uint32_t)__cvta_generic_to_shared(smraw);

    const int qb = (int)gridDim.x - 1 - (int)blockIdx.x;  // longest first
    const int h  = blockIdx.y;
    const int b  = blockIdx.z;
    const int g  = h / REP;

    const int tid = threadIdx.x, lane = tid & 31, warp = tid >> 5;
    const int g4 = lane >> 2, t4 = lane & 3;

    const size_t rs = QKV_COLS;
    const __half* qbase = qkv + ((size_t)b * S_LEN + (size_t)qb * 128) * rs + (size_t)h * HD;
    const __half* kbase = qkv + (size_t)b * S_LEN * rs + (size_t)(NH * HD) + (size_t)g * HD;
    const __half* vbase = kbase + (size_t)(NKV * HD);

    const int lsub  = lane >> 3;
    const int arow  = ((lsub & 1) << 3) + (lane & 7);
    const int acolh = (lsub >> 1) << 3;
    const int krow  = ((lane >> 4) << 3) + (lane & 7);
    const int kcolh = ((lane >> 3) & 1) << 3;
    const int vrow  = lane & 15;
    const int vcolh = (lane >> 4) << 3;

    auto issueKV = [&](int kt, int st) {
        const __half* kb = kbase + (size_t)kt * 64 * rs;
        const __half* vb = vbase + (size_t)kt * 64 * rs;
        const uint32_t kd = sbase + AOFF_ST + st * AST;
        const uint32_t vd = kd + 17408;
#pragma unroll
        for (int i = 0; i < 4; i++) {
            int idx = tid + 256 * i;
            int r = idx >> 4, ch = idx & 15;
            CP_ASYNC16(kd + r * AQ_B + ch * 16, kb + (size_t)r * rs + ch * 8);
            CP_ASYNC16(vd + r * AQ_B + ch * 16, vb + (size_t)r * rs + ch * 8);
        }
        CP_COMMIT();
    };

    const int NT = 2 * qb + 2;       // KV tiles

    // prologue: group0 = Q + KV0; then KV1; then KV2 if present
    {
#pragma unroll
        for (int i = 0; i < 8; i++) {
            int idx = tid + 256 * i;
            int r = idx >> 4, ch = idx & 15;
            CP_ASYNC16(sbase + AOFF_Q + r * AQ_B + ch * 16, qbase + (size_t)r * rs + ch * 8);
        }
        const uint32_t kd = sbase + AOFF_ST;
        const uint32_t vd = kd + 17408;
#pragma unroll
        for (int i = 0; i < 4; i++) {
            int idx = tid + 256 * i;
            int r = idx >> 4, ch = idx & 15;
            CP_ASYNC16(kd + r * AQ_B + ch * 16, kbase + (size_t)r * rs + ch * 8);
            CP_ASYNC16(vd + r * AQ_B + ch * 16, vbase + (size_t)r * rs + ch * 8);
        }
        CP_COMMIT();
    }
    issueKV(1, 1);
    int issued = 2;
    if (NT > 2) { issueKV(2, 2); issued = 3; }

    float m0 = -1e30f, m1 = -1e30f, l0 = 0.0f, l1 = 0.0f;
    float c0p = 0.0f, c1p = 0.0f;     // corr from previous softmax
    uint32_t pp[16];                  // packed P(kt-1) fragments
    float o[16][4];
#pragma unroll
    for (int nt = 0; nt < 16; nt++)
#pragma unroll
        for (int r = 0; r < 4; r++) o[nt][r] = 0.0f;

    const uint32_t aQ = sbase + AOFF_Q + (warp * 16 + arow) * AQ_B + acolh * 2;
    const int grow0 = qb * 128 + warp * 16 + g4;

    for (int kt = 0; kt < NT; kt++) {
        // wait tile kt arrived (allow later prefetches to stay in flight)
        {
            int rem = issued - kt - 1;
            if (rem >= 2) { CP_WAIT2(); } else if (rem == 1) { CP_WAIT1(); } else { CP_WAIT0(); }
        }
        __syncthreads();   // tile kt visible; all warps finished iter kt-1

        // prefetch (stage of tile issued-4 is provably consumed)
        if (issued < NT && issued <= kt + 2) { issueKV(issued, issued & 3); issued++; }

        // ---- S(kt) = Q K^T ----
        const uint32_t bK = sbase + AOFF_ST + (kt & 3) * AST + krow * AQ_B + kcolh * 2;
        float sfr[8][4];
#pragma unroll
        for (int nt = 0; nt < 8; nt++)
#pragma unroll
            for (int r = 0; r < 4; r++) sfr[nt][r] = 0.0f;
#pragma unroll
        for (int ks = 0; ks < 8; ks++) {
            uint32_t af[4];
            ldsm4(af, aQ + ks * 32);
#pragma unroll
            for (int nt2 = 0; nt2 < 4; nt2++) {
                uint32_t bb[4];
                ldsm4(bb, bK + nt2 * 16 * AQ_B + ks * 32);
                mma_f16(sfr[2 * nt2],     af, &bb[0]);
                mma_f16(sfr[2 * nt2 + 1], af, &bb[2]);
            }
        }

        // ---- PV(kt-1): independent tensor work, interleaves with softmax below ----
        if (kt > 0) {
            const uint32_t bV = sbase + AOFF_ST + ((kt - 1) & 3) * AST + 17408 +
                                vrow * AQ_B + vcolh * 2;
#pragma unroll
            for (int nt = 0; nt < 16; nt++) {
                o[nt][0] *= c0p; o[nt][1] *= c0p;
                o[nt][2] *= c1p; o[nt][3] *= c1p;
            }
#pragma unroll
            for (int kk = 0; kk < 4; kk++) {
#pragma unroll
                for (int tt = 0; tt < 8; tt++) {
                    uint32_t v[4];
                    ldsm4t(v, bV + kk * 16 * AQ_B + tt * 32);
                    mma_f16(o[2 * tt],     pp + 4 * kk, &v[0]);
                    mma_f16(o[2 * tt + 1], pp + 4 * kk, &v[2]);
                }
            }
        }

        // ---- softmax(kt): softcap + causal + quad-reduce; writes pp/corr ----
        const bool diag = (kt >= 2 * qb);
        float mx0 = -1e30f, mx1 = -1e30f;
#pragma unroll
        for (int nt = 0; nt < 8; nt++) {
            int gk = kt * 64 + nt * 8 + 2 * t4;
#pragma unroll
            for (int j = 0; j < 2; j++) {
                float y0 = sfr[nt][j] * (SCALE_F / SOFTCAP_F);
                float y1 = sfr[nt][2 + j] * (SCALE_F / SOFTCAP_F);
                float u0 = __expf(-2.0f * y0);
                float u1 = __expf(-2.0f * y1);
                float v0 = SOFTCAP_F * __fdividef(1.0f - u0, 1.0f + u0);
                float v1 = SOFTCAP_F * __fdividef(1.0f - u1, 1.0f + u1);
                if (diag && (gk + j) > grow0)     v0 = -1e30f;
                if (diag && (gk + j) > grow0 + 8) v1 = -1e30f;
                sfr[nt][j] = v0; sfr[nt][2 + j] = v1;
                mx0 = fmaxf(mx0, v0); mx1 = fmaxf(mx1, v1);
            }
        }
        mx0 = fmaxf(mx0, __shfl_xor_sync(0xffffffffu, mx0, 1));
        mx0 = fmaxf(mx0, __shfl_xor_sync(0xffffffffu, mx0, 2));
        mx1 = fmaxf(mx1, __shfl_xor_sync(0xffffffffu, mx1, 1));
        mx1 = fmaxf(mx1, __shfl_xor_sync(0xffffffffu, mx1, 2));

        float mn0 = fmaxf(m0, mx0);
        float mn1 = fmaxf(m1, mx1);
        c0p = __expf(m0 - mn0);
        c1p = __expf(m1 - mn1);
        m0 = mn0; m1 = mn1;

        float sum0 = 0.0f, sum1 = 0.0f;
#pragma unroll
        for (int nt = 0; nt < 8; nt++) {
            float p00 = __expf(sfr[nt][0] - mn0);
            float p01 = __expf(sfr[nt][1] - mn0);
            float p10 = __expf(sfr[nt][2] - mn1);
            float p11 = __expf(sfr[nt][3] - mn1);
            sum0 += p00 + p01; sum1 += p10 + p11;
            int kk = nt >> 1, half = nt & 1;   // pack: pp[4*kk + 2*half + {0,1}]
            pp[4 * kk + 2 * half]     = packh2(p00, p01);
            pp[4 * kk + 2 * half + 1] = packh2(p10, p11);
        }
        l0 = l0 * c0p + sum0;
        l1 = l1 * c1p + sum1;
    }

    // final PV(NT-1)
    {
        const uint32_t bV = sbase + AOFF_ST + ((NT - 1) & 3) * AST + 17408 +
                            vrow * AQ_B + vcolh * 2;
#pragma unroll
        for (int nt = 0; nt < 16; nt++) {
            o[nt][0] *= c0p; o[nt][1] *= c0p;
            o[nt][2] *= c1p; o[nt][3] *= c1p;
        }
#pragma unroll
        for (int kk = 0; kk < 4; kk++) {
#pragma unroll
            for (int tt = 0; tt < 8; tt++) {
                uint32_t v[4];
                ldsm4t(v, bV + kk * 16 * AQ_B + tt * 32);
                mma_f16(o[2 * tt],     pp + 4 * kk, &v[0]);
                mma_f16(o[2 * tt + 1], pp + 4 * kk, &v[2]);
            }
        }
    }

    // finalize: quad-reduce l, normalize, write
    l0 += __shfl_xor_sync(0xffffffffu, l0, 1);
    l0 += __shfl_xor_sync(0xffffffffu, l0, 2);
    l1 += __shfl_xor_sync(0xffffffffu, l1, 1);
    l1 += __shfl_xor_sync(0xffffffffu, l1, 2);
    float inv0 = 1.0f / l0;
    float inv1 = 1.0f / l1;

    size_t gr0 = (size_t)b * S_LEN + grow0;
#pragma unroll
    for (int nt = 0; nt < 16; nt++) {
        int c = h * HD + nt * 8 + 2 * t4;
        *(__half2*)(out + gr0 * HIDDEN + c)       = __floats2half2_rn(o[nt][0] * inv0, o[nt][1] * inv0);
        *(__half2*)(out + (gr0 + 8) * HIDDEN + c) = __floats2half2_rn(o[nt][2] * inv1, o[nt][3] * inv1);
    }
}

// ---------------------------------------------------------------------------
// Launch
// ---------------------------------------------------------------------------
extern "C" void kernel_launch(void* const* d_in, const int* in_sizes, int n_in,
                              void* d_out, int out_size) {
    (void)in_sizes; (void)n_in; (void)out_size;
    const float* hidden = (const float*)d_in[0];
    const float* Wqkv   = (const float*)d_in[1];
    const float* Wo     = (const float*)d_in[2];
    float* out = (float*)d_out;

    void* p;
    cudaGetSymbolAddress(&p, g_hh);    __half* hh    = (__half*)p;
    cudaGetSymbolAddress(&p, g_wqkvh); __half* wqkvh = (__half*)p;
    cudaGetSymbolAddress(&p, g_woh);   __half* woh   = (__half*)p;
    cudaGetSymbolAddress(&p, g_qkvh);  __half* qkvh  = (__half*)p;
    cudaGetSymbolAddress(&p, g_attnh); __half* attnh = (__half*)p;

    cudaFuncSetAttribute(attn_kernel, cudaFuncAttributeMaxDynamicSharedMemorySize,
                         ATTN_SMEM_BYTES);
    cudaFuncSetAttribute(gemm_f16<true>, cudaFuncAttributeMaxDynamicSharedMemorySize,
                         GEMM_SMEM_BYTES);
    cudaFuncSetAttribute(gemm_f16<false>, cudaFuncAttributeMaxDynamicSharedMemorySize,
                         GEMM_SMEM_BYTES);

    rope_table_kernel<<<64, 32>>>();

    // convert inputs to half
    {
        int n8;
        n8 = ROWS * HIDDEN / 8;
        f2h_kernel<<<(n8 + 255) / 256, 256>>>(hidden, hh, n8);
        n8 = HIDDEN * QKV_COLS / 8;
        f2h_kernel<<<(n8 + 255) / 256, 256>>>(Wqkv, wqkvh, n8);
        n8 = HIDDEN * HIDDEN / 8;
        f2h_kernel<<<(n8 + 255) / 256, 256>>>(Wo, woh, n8);
    }

    // 1) QKV projection (half output)
    gemm_f16<true><<<dim3(QKV_COLS / 128, ROWS / 128), 256, GEMM_SMEM_BYTES>>>(
        hh, wqkvh, qkvh, ROWS, QKV_COLS, HIDDEN);
    // 2) RoPE on Q + K in place
    {
        int total = ROWS * 18 * 32;
        rope_apply_h<<<(total + 255) / 256, 256>>>(qkvh);
    }
    // 3) Flash attention (delayed-PV pipeline)
    attn_kernel<<<dim3(S_LEN / 128, NH, BATCH), 256, ATTN_SMEM_BYTES>>>(qkvh, attnh);

    // 4) Output projection (float output)
    gemm_f16<false><<<dim3(HIDDEN / 128, ROWS / 128), 256, GEMM_SMEM_BYTES>>>(
        attnh, woh, out, ROWS, HIDDEN, HIDDEN);
}